// round 15
// baseline (speedup 1.0000x reference)
#include <cuda_runtime.h>
#include <cuda_bf16.h>
#include <cstdint>

// Problem constants
#define Bb   16
#define Cc   1024
#define Nn   32
#define Hh   8
#define Dd   128
#define NP   (Bb*Cc)          // 16384 (b,c) pairs
#define QSCALE 0.25f          // Dh^-0.5 = 16^-0.5
#define PB   4                // pairs per k_main block

// Scratch (device globals — no runtime allocation allowed)
__device__ float g_query[(size_t)NP * Dd];           // 8 MB
__device__ float g_wsum[(size_t)NP * Hh * Dd];       // 64 MB
__device__ float g_asum[(size_t)NP * Hh];            // 512 KB

// ---- packed fp32x2 helpers (Blackwell FFMA2) -------------------------------
typedef unsigned long long ull;
__device__ __forceinline__ ull fma2(ull a, ull b, ull c) {
    ull d; asm("fma.rn.f32x2 %0, %1, %2, %3;" : "=l"(d) : "l"(a), "l"(b), "l"(c));
    return d;
}
__device__ __forceinline__ ull pk2(float lo, float hi) {
    ull r; asm("mov.b64 %0, {%1, %2};" : "=l"(r) : "f"(lo), "f"(hi)); return r;
}
__device__ __forceinline__ float2 upk2(ull v) {
    float2 r; asm("mov.b64 {%0, %1}, %2;" : "=f"(r.x), "=f"(r.y) : "l"(v)); return r;
}
#define U64(d) __double_as_longlong(d)

// ---------------------------------------------------------------------------
// K1 v2: query[p,d] = atom_query[p,:] @ Wq + bq   (32 pairs per block)
// Wq staged over f in 2 halves (64 x 128); pitch 128 everywhere (reads are
// broadcast or lane-contiguous float4 -> conflict-free without padding).
// smem = 12416 floats = 49664 B -> 4 CTAs/SM (32 warps)
// ---------------------------------------------------------------------------
__global__ __launch_bounds__(256, 4) void k_query(const float* __restrict__ aq,
                                                  const float* __restrict__ Wq,
                                                  const float* __restrict__ bq)
{
    extern __shared__ float sm[];
    float* Wq_s = sm;                  // 64*128 = 8192
    float* aq_s = sm + 8192;           // 32*128 = 4096
    float* bq_s = sm + 12288;          // 128
    const int t = threadIdx.x;
    const int p0 = blockIdx.x * 32;

    #pragma unroll
    for (int j = 0; j < 4; j++) {
        int i4 = t + j * 256;                      // 0..1023
        ((float4*)aq_s)[i4] = ((const float4*)(aq + (size_t)p0 * Dd))[i4];
    }
    if (t < 128) bq_s[t] = bq[t];

    const int w = t >> 5, lane = t & 31;
    const int pl0 = w * 4, d0 = lane * 4;
    ull acc[4][2];
    #pragma unroll
    for (int k = 0; k < 4; k++) { acc[k][0] = 0ULL; acc[k][1] = 0ULL; }

    #pragma unroll
    for (int s = 0; s < 2; s++) {
        __syncthreads();   // s=0: covers aq/bq stores; s>0: Wq_s reuse
        #pragma unroll
        for (int j = 0; j < 8; j++) {
            int i4 = t + j * 256;                  // 0..2047: fl = i4>>5, d4 = i4&31
            ((float4*)Wq_s)[i4] =
                ((const float4*)Wq)[(s * 64 + (i4 >> 5)) * 32 + (i4 & 31)];
        }
        __syncthreads();
        #pragma unroll 8
        for (int fl = 0; fl < 64; fl++) {
            double2 wv = *(double2*)&Wq_s[fl * 128 + d0];   // LDS.128 conflict-free
            #pragma unroll
            for (int k = 0; k < 4; k++) {
                float a = aq_s[(pl0 + k) * 128 + s * 64 + fl];  // broadcast
                ull a2 = pk2(a, a);
                acc[k][0] = fma2(a2, U64(wv.x), acc[k][0]);
                acc[k][1] = fma2(a2, U64(wv.y), acc[k][1]);
            }
        }
    }
    float4 b4 = *(float4*)&bq_s[d0];
    #pragma unroll
    for (int k = 0; k < 4; k++) {
        float2 lo = upk2(acc[k][0]), hi = upk2(acc[k][1]);
        float4 r = { lo.x + b4.x, lo.y + b4.y, hi.x + b4.z, hi.y + b4.w };
        *(float4*)&g_query[(size_t)(p0 + pl0 + k) * Dd + d0] = r;
    }
}

// ---------------------------------------------------------------------------
// K2 v4 (R13-exact): 4 pairs per block, 4 CTAs/SM (32 warps). Wk in 4
// quarter-stages, Wf/bf in registers, an-tile+dist prefetch.
// smem = 10784 floats = 43136 B
// ---------------------------------------------------------------------------
__global__ __launch_bounds__(256, 4) void k_main(const float* __restrict__ anb,
                                                 const float* __restrict__ ldist,
                                                 const float* __restrict__ maskp,
                                                 const float* __restrict__ Wk,
                                                 const float* __restrict__ bk,
                                                 const float* __restrict__ Wf,
                                                 const float* __restrict__ bf,
                                                 float* __restrict__ attn_out)
{
    extern __shared__ float sm[];
    // persistent
    float* qk_s = sm;                    // 4p*8h rows * 128 = 4096
    float* eb_s = sm + 4096;             // 32
    float* U    = sm + 4128;             // union (6656 floats)
    // phase 1 view
    float* Wst_s   = U;                  // 128e * 36 = 4608 (quarter stage)
    float* query_s = U + 4608;           // 4*132 = 528
    float* bk_s    = U + 5136;           // 128
    // phase 2 view
    float* an_s   = U;                   // 32*132 = 4224
    float* epart  = U + 4224;            // 8w*8h*32n = 2048
    float* attn_s = U + 6272;            // 32*12 = 384  [n*12 + h]

    const int t = threadIdx.x;
    const int p0 = blockIdx.x * PB;
    const int w = t >> 5, lane = t & 31;

    // per-thread gate params (thread only ever touches e = 4*(t&31)..+3)
    const float4 Wf4 = ((const float4*)Wf)[t & 31];
    const float4 bf4 = ((const float4*)bf)[t & 31];

    if (t < 128) bk_s[t] = bk[t];
    if (t < 128) {   // query for 4 pairs (512 floats = 128 float4), pitch 132
        int pl = t >> 5, e4 = t & 31;
        float4 v = ((const float4*)(g_query + (size_t)p0 * Dd))[t];
        *(float4*)&query_s[pl * 132 + e4 * 4] = v;
    }

    // ---- qk: 4 quarter-stages of Wk, each covers 2 heads (32 out-dims)
    const int e_col = t & 127, hl = t >> 7;
    #pragma unroll
    for (int s = 0; s < 4; s++) {
        __syncthreads();   // s=0: covers query/bk stores; s>0: Wst reuse
        #pragma unroll
        for (int j = 0; j < 4; j++) {
            int idx = t + j * 256;                  // 0..1023
            int e = idx >> 3, q = idx & 7;          // 8 float4 per e-row
            float4 v = ((const float4*)Wk)[e * 32 + s * 8 + q];
            *(float4*)&Wst_s[e * 36 + q * 4] = v;
        }
        __syncthreads();
        const int h = s * 2 + hl;
        ull wk2[8];
        #pragma unroll
        for (int i = 0; i < 4; i++) {
            double2 w2 = *(double2*)&Wst_s[e_col * 36 + hl * 16 + i * 4];
            wk2[i * 2 + 0] = U64(w2.x);
            wk2[i * 2 + 1] = U64(w2.y);
        }
        #pragma unroll
        for (int p = 0; p < PB; p++) {
            ull acc2 = 0ULL;
            #pragma unroll
            for (int i = 0; i < 4; i++) {
                double2 q2 = *(double2*)&query_s[p * 132 + h * 16 + i * 4]; // bcast
                acc2 = fma2(wk2[i * 2 + 0], U64(q2.x), acc2);
                acc2 = fma2(wk2[i * 2 + 1], U64(q2.y), acc2);
            }
            float2 a = upk2(acc2);
            qk_s[(p * 8 + h) * 128 + e_col] = (a.x + a.y) * QSCALE;
        }
    }
    __syncthreads();
    // energy bias eb[p,h] = scaled q . bk  (query_s/bk_s still valid)
    if (t < 8 * PB) {
        int p = t >> 3, h = t & 7;
        float acc = 0.f;
        #pragma unroll
        for (int dd = 0; dd < 16; dd++)
            acc += query_s[p * 132 + h * 16 + dd] * bk_s[h * 16 + dd];
        eb_s[t] = acc * QSCALE;
    }
    __syncthreads();

    // prefetch for pair 0
    float4 pf[4]; float pfd[4]; float pm;
    {
        const float4* anp = (const float4*)(anb + (size_t)p0 * (Nn * Dd));
        #pragma unroll
        for (int j = 0; j < 4; j++) {
            int i4 = t + j * 256;
            pf[j] = anp[i4];
            pfd[j] = __ldg(&ldist[(size_t)p0 * Nn + (i4 >> 5)]);
        }
        pm = __ldg(&maskp[(size_t)p0 * Nn + lane]);
    }

    for (int pl = 0; pl < PB; pl++) {
        const size_t p = (size_t)(p0 + pl);
        const float pm_cur = pm;

        // ---- A: gated an: an[n,e] = anb * swish(dist*Wf+bf)
        #pragma unroll
        for (int j = 0; j < 4; j++) {
            int n = (t + j * 256) >> 5;
            float4 v = pf[j];
            float dval = pfd[j];
            float x0 = fmaf(dval, Wf4.x, bf4.x);
            float x1 = fmaf(dval, Wf4.y, bf4.y);
            float x2 = fmaf(dval, Wf4.z, bf4.z);
            float x3 = fmaf(dval, Wf4.w, bf4.w);
            float4 g;
            g.x = v.x * __fdividef(x0, 1.f + __expf(-x0));
            g.y = v.y * __fdividef(x1, 1.f + __expf(-x1));
            g.z = v.z * __fdividef(x2, 1.f + __expf(-x2));
            g.w = v.w * __fdividef(x3, 1.f + __expf(-x3));
            *(float4*)&an_s[n * 132 + (t & 31) * 4] = g;
        }
        __syncthreads();

        // prefetch next pair while B/C/D run
        if (pl < PB - 1) {
            const float4* anp = (const float4*)(anb + (p + 1) * (Nn * Dd));
            #pragma unroll
            for (int j = 0; j < 4; j++) {
                int i4 = t + j * 256;
                pf[j] = anp[i4];
                pfd[j] = __ldg(&ldist[(p + 1) * Nn + (i4 >> 5)]);
            }
            pm = __ldg(&maskp[(p + 1) * Nn + lane]);
        }

        // ---- B: energy partials — warp w owns e-chunk [w*16,+16), lane = n
        {
            ull a2[8];
            #pragma unroll
            for (int i = 0; i < 4; i++) {
                double2 av = *(double2*)&an_s[lane * 132 + w * 16 + i * 4];
                a2[i * 2 + 0] = U64(av.x);
                a2[i * 2 + 1] = U64(av.y);
            }
            const float* qkp = &qk_s[pl * 8 * 128 + w * 16];
            #pragma unroll
            for (int h = 0; h < 8; h++) {
                ull acc2 = 0ULL;
                #pragma unroll
                for (int i = 0; i < 4; i++) {
                    double2 q2 = *(const double2*)&qkp[h * 128 + i * 4]; // bcast
                    acc2 = fma2(a2[i * 2 + 0], U64(q2.x), acc2);
                    acc2 = fma2(a2[i * 2 + 1], U64(q2.y), acc2);
                }
                float2 a = upk2(acc2);
                epart[(w * 8 + h) * 32 + lane] = a.x + a.y;
            }
        }
        __syncthreads();

        // ---- C: reduce + softmax over n (no max pass): warp w = head, lane = n
        {
            const int h = w, n = lane;
            float en = eb_s[pl * 8 + h];
            #pragma unroll
            for (int wc = 0; wc < 8; wc++) en += epart[(wc * 8 + h) * 32 + n];
            en += (1.f - pm_cur) * (-1e9f);
            float ex = __expf(en);
            float exm = ex * pm_cur;
            float s = ex, smm = exm;
            #pragma unroll
            for (int o = 16; o > 0; o >>= 1) {
                s   += __shfl_xor_sync(0xffffffffu, s, o);
                smm += __shfl_xor_sync(0xffffffffu, smm, o);
            }
            float rinv = __fdividef(1.f, s);
            float at = ex * rinv;
            if (attn_out) {
                int b = (int)(p >> 10), c = (int)(p & 1023);
                attn_out[((size_t)(b * Hh + h) * Cc + c) * Nn + n] = at;
            }
            attn_s[n * 12 + h] = at * pm_cur;
            if (n == 0) g_asum[p * Hh + h] = smm * rinv;
        }
        __syncthreads();

        // ---- D: wsum[h,e] = sum_n attnm[h,n]*an[n,e]; thread = (e, h-half)
        {
            const int e = t & 127, hh = t >> 7;
            ull acc01 = 0ULL, acc23 = 0ULL;
            #pragma unroll 8
            for (int n = 0; n < 32; n++) {
                float av = an_s[n * 132 + e];                      // conflict-free
                ull av2 = pk2(av, av);
                double2 at2 = *(double2*)&attn_s[n * 12 + hh * 4]; // bcast LDS.128
                acc01 = fma2(av2, U64(at2.x), acc01);
                acc23 = fma2(av2, U64(at2.y), acc23);
            }
            float2 a01 = upk2(acc01), a23 = upk2(acc23);
            float* wout = &g_wsum[(p * Hh + hh * 4) * Dd + e];
            wout[0] = a01.x; wout[128] = a01.y; wout[256] = a23.x; wout[384] = a23.y;
        }
        __syncthreads();
    }
}

// ---------------------------------------------------------------------------
// K3 v4: context = wsum @ Wv + asum*bv + query
// 8 pairs per block (warp = one pair), Wv via coalesced LDG.128 from L1.
// smem = 8640 floats = 34560 B -> occupancy reg-limited (~5-6 CTAs, 40-48 warps)
// ---------------------------------------------------------------------------
__global__ __launch_bounds__(256) void k_ctx(const float* __restrict__ Wv,
                                             const float* __restrict__ bv,
                                             float* __restrict__ ctx_out)
{
    extern __shared__ float sm[];
    float* ws_s   = sm;                  // 64 rows (8p*8h) * 132 = 8448
    float* asum_s = sm + 8448;           // 64
    float* bv_s   = sm + 8512;           // 128

    const int t = threadIdx.x;
    const int p0 = blockIdx.x * 8;

    #pragma unroll
    for (int j = 0; j < 8; j++) {
        int i4 = t + j * 256;                       // 2048 float4 = 8p*8h*32
        int row = i4 >> 5, e4 = i4 & 31;
        float4 v = ((const float4*)(g_wsum + (size_t)p0 * Hh * Dd))[i4];
        *(float4*)&ws_s[row * 132 + e4 * 4] = v;
    }
    if (t < 64)  asum_s[t] = g_asum[(size_t)p0 * Hh + t];
    if (t < 128) bv_s[t] = bv[t];
    __syncthreads();

    const int w = t >> 5, lane = t & 31;
    const int h = lane >> 2, dd0 = (lane & 3) * 4;
    // Wv row-major [e][d]; double2 = 4 floats -> row stride 32 double2.
    const double2* wvp = (const double2*)&Wv[h * 16 + dd0];

    ull a01 = 0ULL, a23 = 0ULL;

    #pragma unroll 4
    for (int e4 = 0; e4 < 32; e4++) {
        float s0[4];
        *(float4*)s0 = *(float4*)&ws_s[(w * 8 + h) * 132 + e4 * 4]; // dedup LDS.128
        #pragma unroll
        for (int j = 0; j < 4; j++) {
            double2 wv = __ldg(&wvp[(e4 * 4 + j) * 32]);   // coalesced LDG.128, L1-hot
            ull v0 = pk2(s0[j], s0[j]);
            a01 = fma2(v0, U64(wv.x), a01);
            a23 = fma2(v0, U64(wv.y), a23);
        }
    }

    float4 b4 = *(const float4*)&bv_s[h * 16 + dd0];
    float as = asum_s[w * 8 + h];
    float4 q4 = *(const float4*)&g_query[(size_t)(p0 + w) * Dd + h * 16 + dd0];
    float2 lo = upk2(a01), hi = upk2(a23);
    float4 r;
    r.x = lo.x + as * b4.x + q4.x;
    r.y = lo.y + as * b4.y + q4.y;
    r.z = hi.x + as * b4.z + q4.z;
    r.w = hi.y + as * b4.w + q4.w;
    *(float4*)&ctx_out[(size_t)(p0 + w) * Dd + h * 16 + dd0] = r;
}

// ---------------------------------------------------------------------------
extern "C" void kernel_launch(void* const* d_in, const int* in_sizes, int n_in,
                              void* d_out, int out_size)
{
    const float* aq    = (const float*)d_in[0];
    const float* anb   = (const float*)d_in[1];
    const float* ldist = (const float*)d_in[2];
    const float* maskp = (const float*)d_in[3];
    const float* Wq    = (const float*)d_in[4];
    const float* bq    = (const float*)d_in[5];
    const float* Wk    = (const float*)d_in[6];
    const float* bk    = (const float*)d_in[7];
    const float* Wv    = (const float*)d_in[8];
    const float* bv    = (const float*)d_in[9];
    const float* Wf    = (const float*)d_in[10];
    const float* bf    = (const float*)d_in[11];

    float* out = (float*)d_out;
    const size_t attn_elems = (size_t)NP * Hh * Nn;   // 4194304
    const size_t ctx_elems  = (size_t)NP * Dd;        // 2097152
    float* attn_out = nullptr;
    float* ctx_out  = nullptr;
    if ((size_t)out_size >= attn_elems + ctx_elems) { attn_out = out; ctx_out = out + attn_elems; }
    else if ((size_t)out_size == attn_elems)        { attn_out = out; }
    else                                            { ctx_out = out; }

    const int SM1 = 12416 * 4;                          // 49664
    const int SM2 = 10784 * 4;                          // 43136
    const int SM3 = 8640 * 4;                           // 34560

    cudaFuncSetAttribute(k_query, cudaFuncAttributeMaxDynamicSharedMemorySize, SM1);
    cudaFuncSetAttribute(k_main,  cudaFuncAttributeMaxDynamicSharedMemorySize, SM2);
    cudaFuncSetAttribute(k_ctx,   cudaFuncAttributeMaxDynamicSharedMemorySize, SM3);

    k_query<<<NP / 32, 256, SM1>>>(aq, Wq, bq);
    k_main<<<NP / PB, 256, SM2>>>(anb, ldist, maskp, Wk, bk, Wf, bf, attn_out);
    if (ctx_out)
        k_ctx<<<NP / 8, 256, SM3>>>(Wv, bv, ctx_out);
}

// round 17
// speedup vs baseline: 1.0784x; 1.0784x over previous
#include <cuda_runtime.h>
#include <cuda_bf16.h>
#include <cstdint>

// Problem constants
#define Bb   16
#define Cc   1024
#define Nn   32
#define Hh   8
#define Dd   128
#define NP   (Bb*Cc)          // 16384 (b,c) pairs
#define QSCALE 0.25f          // Dh^-0.5 = 16^-0.5
#define PB   4                // pairs per k_main block

// Scratch (device globals — no runtime allocation allowed)
__device__ float g_query[(size_t)NP * Dd];           // 8 MB

// ---- packed fp32x2 helpers (Blackwell FFMA2) -------------------------------
typedef unsigned long long ull;
__device__ __forceinline__ ull fma2(ull a, ull b, ull c) {
    ull d; asm("fma.rn.f32x2 %0, %1, %2, %3;" : "=l"(d) : "l"(a), "l"(b), "l"(c));
    return d;
}
__device__ __forceinline__ ull pk2(float lo, float hi) {
    ull r; asm("mov.b64 %0, {%1, %2};" : "=l"(r) : "f"(lo), "f"(hi)); return r;
}
__device__ __forceinline__ float2 upk2(ull v) {
    float2 r; asm("mov.b64 {%0, %1}, %2;" : "=f"(r.x), "=f"(r.y) : "l"(v)); return r;
}
#define U64(d) __double_as_longlong(d)

// ---------------------------------------------------------------------------
// K1 v2: query[p,d] = atom_query[p,:] @ Wq + bq   (32 pairs per block)
// Wq staged over f in 2 halves (64 x 128); pitch 128 (conflict-free).
// smem = 12416 floats = 49664 B -> 4 CTAs/SM
// ---------------------------------------------------------------------------
__global__ __launch_bounds__(256, 4) void k_query(const float* __restrict__ aq,
                                                  const float* __restrict__ Wq,
                                                  const float* __restrict__ bq)
{
    extern __shared__ float sm[];
    float* Wq_s = sm;                  // 64*128 = 8192
    float* aq_s = sm + 8192;           // 32*128 = 4096
    float* bq_s = sm + 12288;          // 128
    const int t = threadIdx.x;
    const int p0 = blockIdx.x * 32;

    #pragma unroll
    for (int j = 0; j < 4; j++) {
        int i4 = t + j * 256;                      // 0..1023
        ((float4*)aq_s)[i4] = ((const float4*)(aq + (size_t)p0 * Dd))[i4];
    }
    if (t < 128) bq_s[t] = bq[t];

    const int w = t >> 5, lane = t & 31;
    const int pl0 = w * 4, d0 = lane * 4;
    ull acc[4][2];
    #pragma unroll
    for (int k = 0; k < 4; k++) { acc[k][0] = 0ULL; acc[k][1] = 0ULL; }

    #pragma unroll
    for (int s = 0; s < 2; s++) {
        __syncthreads();   // s=0: covers aq/bq stores; s>0: Wq_s reuse
        #pragma unroll
        for (int j = 0; j < 8; j++) {
            int i4 = t + j * 256;                  // 0..2047
            ((float4*)Wq_s)[i4] =
                ((const float4*)Wq)[(s * 64 + (i4 >> 5)) * 32 + (i4 & 31)];
        }
        __syncthreads();
        #pragma unroll 8
        for (int fl = 0; fl < 64; fl++) {
            double2 wv = *(double2*)&Wq_s[fl * 128 + d0];   // LDS.128 conflict-free
            #pragma unroll
            for (int k = 0; k < 4; k++) {
                float a = aq_s[(pl0 + k) * 128 + s * 64 + fl];  // broadcast
                ull a2 = pk2(a, a);
                acc[k][0] = fma2(a2, U64(wv.x), acc[k][0]);
                acc[k][1] = fma2(a2, U64(wv.y), acc[k][1]);
            }
        }
    }
    float4 b4 = *(float4*)&bq_s[d0];
    #pragma unroll
    for (int k = 0; k < 4; k++) {
        float2 lo = upk2(acc[k][0]), hi = upk2(acc[k][1]);
        float4 r = { lo.x + b4.x, lo.y + b4.y, hi.x + b4.z, hi.y + b4.w };
        *(float4*)&g_query[(size_t)(p0 + pl0 + k) * Dd + d0] = r;
    }
}

// ---------------------------------------------------------------------------
// K2 v6 (fused): per 4-pair block, per pair: A gated an -> B energy partials
// -> C softmax -> D wsum (to smem) -> E context = wsum@Wv + asum*bv + query.
// Wv read via coalesced L1-hot LDG.64 (shared across 4 CTAs/SM).
// smem = 11976 floats = 47904 B -> 4 CTAs/SM (191.6 KB)
// ---------------------------------------------------------------------------
__global__ __launch_bounds__(256, 4) void k_main(const float* __restrict__ anb,
                                                 const float* __restrict__ ldist,
                                                 const float* __restrict__ maskp,
                                                 const float* __restrict__ Wk,
                                                 const float* __restrict__ bk,
                                                 const float* __restrict__ Wv,
                                                 const float* __restrict__ bv,
                                                 const float* __restrict__ Wf,
                                                 const float* __restrict__ bf,
                                                 float* __restrict__ attn_out,
                                                 float* __restrict__ ctx_out)
{
    extern __shared__ float sm[];
    // persistent
    float* qk_s  = sm;                   // 4p*8h rows * 128 = 4096
    float* eb_s  = sm + 4096;            // 32
    float* bv_s  = sm + 4128;            // 128
    float* asw_s = sm + 4256;            // 8 (per-pair asum)
    float* U     = sm + 4264;            // union (7712 floats)
    // phase 1 view
    float* Wst_s   = U;                  // 128e * 36 = 4608 (quarter stage)
    float* query_s = U + 4608;           // 4*132 = 528
    float* bk_s    = U + 5136;           // 128
    // phase 2 view
    float* an_s   = U;                   // 32*132 = 4224
    float* epart  = U + 4224;            // 2048 (B partials; E reduction reuse)
    float* attn_s = U + 6272;            // 32*12 = 384  [n*12 + h]
    float* ws_s   = U + 6656;            // 8h*132 = 1056

    const int t = threadIdx.x;
    const int p0 = blockIdx.x * PB;
    const int w = t >> 5, lane = t & 31;

    // per-thread gate params (thread only ever touches e = 4*(t&31)..+3)
    const float4 Wf4 = ((const float4*)Wf)[t & 31];
    const float4 bf4 = ((const float4*)bf)[t & 31];

    if (t < 128) { bk_s[t] = bk[t]; bv_s[t] = bv[t]; }
    if (t < 128) {   // query for 4 pairs (512 floats = 128 float4), pitch 132
        int pl = t >> 5, e4 = t & 31;
        float4 v = ((const float4*)(g_query + (size_t)p0 * Dd))[t];
        *(float4*)&query_s[pl * 132 + e4 * 4] = v;
    }

    // ---- qk: 4 quarter-stages of Wk, each covers 2 heads (32 out-dims)
    const int e_col = t & 127, hl = t >> 7;
    #pragma unroll
    for (int s = 0; s < 4; s++) {
        __syncthreads();   // s=0: covers query/bk/bv stores; s>0: Wst reuse
        #pragma unroll
        for (int j = 0; j < 4; j++) {
            int idx = t + j * 256;                  // 0..1023
            int e = idx >> 3, q = idx & 7;          // 8 float4 per e-row
            float4 v = ((const float4*)Wk)[e * 32 + s * 8 + q];
            *(float4*)&Wst_s[e * 36 + q * 4] = v;
        }
        __syncthreads();
        const int h = s * 2 + hl;
        ull wk2[8];
        #pragma unroll
        for (int i = 0; i < 4; i++) {
            double2 w2 = *(double2*)&Wst_s[e_col * 36 + hl * 16 + i * 4];
            wk2[i * 2 + 0] = U64(w2.x);
            wk2[i * 2 + 1] = U64(w2.y);
        }
        #pragma unroll
        for (int p = 0; p < PB; p++) {
            ull acc2 = 0ULL;
            #pragma unroll
            for (int i = 0; i < 4; i++) {
                double2 q2 = *(double2*)&query_s[p * 132 + h * 16 + i * 4]; // bcast
                acc2 = fma2(wk2[i * 2 + 0], U64(q2.x), acc2);
                acc2 = fma2(wk2[i * 2 + 1], U64(q2.y), acc2);
            }
            float2 a = upk2(acc2);
            qk_s[(p * 8 + h) * 128 + e_col] = (a.x + a.y) * QSCALE;
        }
    }
    __syncthreads();
    // energy bias eb[p,h] = scaled q . bk  (query_s/bk_s still valid)
    if (t < 8 * PB) {
        int p = t >> 3, h = t & 7;
        float acc = 0.f;
        #pragma unroll
        for (int dd = 0; dd < 16; dd++)
            acc += query_s[p * 132 + h * 16 + dd] * bk_s[h * 16 + dd];
        eb_s[t] = acc * QSCALE;
    }
    __syncthreads();

    // prefetch for pair 0
    float4 pf[4]; float pfd[4]; float pm;
    {
        const float4* anp = (const float4*)(anb + (size_t)p0 * (Nn * Dd));
        #pragma unroll
        for (int j = 0; j < 4; j++) {
            int i4 = t + j * 256;
            pf[j] = anp[i4];
            pfd[j] = __ldg(&ldist[(size_t)p0 * Nn + (i4 >> 5)]);
        }
        pm = __ldg(&maskp[(size_t)p0 * Nn + lane]);
    }

    for (int pl = 0; pl < PB; pl++) {
        const size_t p = (size_t)(p0 + pl);
        const float pm_cur = pm;

        // ---- A: gated an: an[n,e] = anb * swish(dist*Wf+bf)
        #pragma unroll
        for (int j = 0; j < 4; j++) {
            int n = (t + j * 256) >> 5;
            float4 v = pf[j];
            float dval = pfd[j];
            float x0 = fmaf(dval, Wf4.x, bf4.x);
            float x1 = fmaf(dval, Wf4.y, bf4.y);
            float x2 = fmaf(dval, Wf4.z, bf4.z);
            float x3 = fmaf(dval, Wf4.w, bf4.w);
            float4 g;
            g.x = v.x * __fdividef(x0, 1.f + __expf(-x0));
            g.y = v.y * __fdividef(x1, 1.f + __expf(-x1));
            g.z = v.z * __fdividef(x2, 1.f + __expf(-x2));
            g.w = v.w * __fdividef(x3, 1.f + __expf(-x3));
            *(float4*)&an_s[n * 132 + (t & 31) * 4] = g;
        }
        __syncthreads();

        // prefetch next pair while B/C/D/E run
        if (pl < PB - 1) {
            const float4* anp = (const float4*)(anb + (p + 1) * (Nn * Dd));
            #pragma unroll
            for (int j = 0; j < 4; j++) {
                int i4 = t + j * 256;
                pf[j] = anp[i4];
                pfd[j] = __ldg(&ldist[(p + 1) * Nn + (i4 >> 5)]);
            }
            pm = __ldg(&maskp[(p + 1) * Nn + lane]);
        }

        // ---- B: energy partials — warp w owns e-chunk [w*16,+16), lane = n
        {
            ull a2[8];
            #pragma unroll
            for (int i = 0; i < 4; i++) {
                double2 av = *(double2*)&an_s[lane * 132 + w * 16 + i * 4];
                a2[i * 2 + 0] = U64(av.x);
                a2[i * 2 + 1] = U64(av.y);
            }
            const float* qkp = &qk_s[pl * 8 * 128 + w * 16];
            #pragma unroll
            for (int h = 0; h < 8; h++) {
                ull acc2 = 0ULL;
                #pragma unroll
                for (int i = 0; i < 4; i++) {
                    double2 q2 = *(const double2*)&qkp[h * 128 + i * 4]; // bcast
                    acc2 = fma2(a2[i * 2 + 0], U64(q2.x), acc2);
                    acc2 = fma2(a2[i * 2 + 1], U64(q2.y), acc2);
                }
                float2 a = upk2(acc2);
                epart[(w * 8 + h) * 32 + lane] = a.x + a.y;
            }
        }
        __syncthreads();

        // ---- C: reduce + softmax over n (no max pass): warp w = head, lane = n
        {
            const int h = w, n = lane;
            float en = eb_s[pl * 8 + h];
            #pragma unroll
            for (int wc = 0; wc < 8; wc++) en += epart[(wc * 8 + h) * 32 + n];
            en += (1.f - pm_cur) * (-1e9f);
            float ex = __expf(en);
            float exm = ex * pm_cur;
            float s = ex, smm = exm;
            #pragma unroll
            for (int o = 16; o > 0; o >>= 1) {
                s   += __shfl_xor_sync(0xffffffffu, s, o);
                smm += __shfl_xor_sync(0xffffffffu, smm, o);
            }
            float rinv = __fdividef(1.f, s);
            float at = ex * rinv;
            if (attn_out) {
                int b = (int)(p >> 10), c = (int)(p & 1023);
                attn_out[((size_t)(b * Hh + h) * Cc + c) * Nn + n] = at;
            }
            attn_s[n * 12 + h] = at * pm_cur;
            if (n == 0) asw_s[h] = smm * rinv;
        }
        __syncthreads();

        // ---- D: wsum[h,e] = sum_n attnm[h,n]*an[n,e] -> smem; thread = (e,hh)
        {
            const int e = t & 127, hh = t >> 7;
            ull acc01 = 0ULL, acc23 = 0ULL;
            #pragma unroll 8
            for (int n = 0; n < 32; n++) {
                float av = an_s[n * 132 + e];                      // conflict-free
                ull av2 = pk2(av, av);
                double2 at2 = *(double2*)&attn_s[n * 12 + hh * 4]; // bcast LDS.128
                acc01 = fma2(av2, U64(at2.x), acc01);
                acc23 = fma2(av2, U64(at2.y), acc23);
            }
            float2 a01 = upk2(acc01), a23 = upk2(acc23);
            ws_s[(hh * 4 + 0) * 132 + e] = a01.x;
            ws_s[(hh * 4 + 1) * 132 + e] = a01.y;
            ws_s[(hh * 4 + 2) * 132 + e] = a23.x;
            ws_s[(hh * 4 + 3) * 132 + e] = a23.y;
        }
        __syncthreads();

        // ---- E: context[d0,d0+1] = sum_e ws[h,e]*Wv[e,d] + asum*bv + query
        // thread = (dpair = t&63 -> d0 = 2*dpair, e-quarter q = t>>6)
        {
            const int dp = t & 63, q = t >> 6;
            const int d0 = dp * 2, h = dp >> 3;
            const float* wsrow = &ws_s[h * 132 + q * 32];
            const double* wvp2 = (const double*)&Wv[d0];   // [e] -> wvp2[e*64]
            ull acc = 0ULL;
            #pragma unroll 8
            for (int e = 0; e < 32; e++) {
                double wvd = __ldg(&wvp2[(q * 32 + e) * 64]);   // coalesced LDG.64
                float wsv = wsrow[e];                            // 4-addr bcast
                acc = fma2(pk2(wsv, wsv), U64(wvd), acc);
            }
            ull* red = (ull*)epart;                // 3*64 ull, epart free after C
            if (q) red[(q - 1) * 64 + dp] = acc;
            __syncthreads();
            if (q == 0 && ctx_out) {
                float2 r0 = upk2(acc);
                float2 r1 = upk2(red[dp]);
                float2 r2 = upk2(red[64 + dp]);
                float2 r3 = upk2(red[128 + dp]);
                float as = asw_s[h];
                float2 b2 = *(const float2*)&bv_s[d0];
                float2 q2 = *(const float2*)&g_query[p * Dd + d0];
                float2 o2;
                o2.x = (r0.x + r1.x) + (r2.x + r3.x) + as * b2.x + q2.x;
                o2.y = (r0.y + r1.y) + (r2.y + r3.y) + as * b2.y + q2.y;
                *(float2*)&ctx_out[p * Dd + d0] = o2;
            }
        }
        __syncthreads();   // red reads + asw/ws done before next pair reuses U
    }
}

// ---------------------------------------------------------------------------
extern "C" void kernel_launch(void* const* d_in, const int* in_sizes, int n_in,
                              void* d_out, int out_size)
{
    const float* aq    = (const float*)d_in[0];
    const float* anb   = (const float*)d_in[1];
    const float* ldist = (const float*)d_in[2];
    const float* maskp = (const float*)d_in[3];
    const float* Wq    = (const float*)d_in[4];
    const float* bq    = (const float*)d_in[5];
    const float* Wk    = (const float*)d_in[6];
    const float* bk    = (const float*)d_in[7];
    const float* Wv    = (const float*)d_in[8];
    const float* bv    = (const float*)d_in[9];
    const float* Wf    = (const float*)d_in[10];
    const float* bf    = (const float*)d_in[11];

    float* out = (float*)d_out;
    const size_t attn_elems = (size_t)NP * Hh * Nn;   // 4194304
    const size_t ctx_elems  = (size_t)NP * Dd;        // 2097152
    float* attn_out = nullptr;
    float* ctx_out  = nullptr;
    if ((size_t)out_size >= attn_elems + ctx_elems) { attn_out = out; ctx_out = out + attn_elems; }
    else if ((size_t)out_size == attn_elems)        { attn_out = out; }
    else                                            { ctx_out = out; }

    const int SM1 = 12416 * 4;                          // 49664
    const int SM2 = 11976 * 4;                          // 47904

    cudaFuncSetAttribute(k_query, cudaFuncAttributeMaxDynamicSharedMemorySize, SM1);
    cudaFuncSetAttribute(k_main,  cudaFuncAttributeMaxDynamicSharedMemorySize, SM2);

    k_query<<<NP / 32, 256, SM1>>>(aq, Wq, bq);
    k_main<<<NP / PB, 256, SM2>>>(anb, ldist, maskp, Wk, bk, Wv, bv, Wf, bf,
                                  attn_out, ctx_out);
}